// round 4
// baseline (speedup 1.0000x reference)
#include <cuda_runtime.h>
#include <cstdint>

#define B_   4
#define C_   256
#define H_   128
#define W_   128
#define Q_   100
#define OUT_ 7
#define BINS (OUT_ * OUT_)   // 49

#define YT_  8               // rows per y-tile
#define NT_  (H_ / YT_)      // 16 y-tiles
#define CG1_ 8               // channels per K1 block
#define NCG1_ (C_ / CG1_)    // 32

// Tile-local SAT (y-scanned within 8-row tiles), channel-last: S[b][y][x][c]
__device__ float g_sat[(size_t)B_ * H_ * W_ * C_];            // 64 MB
// Per-tile column sums / exclusive tile prefix: [b][t][x][c]
__device__ float g_cs [(size_t)B_ * NT_ * W_ * C_];           // 8 MB
__device__ float g_off[(size_t)B_ * NT_ * W_ * C_];           // 8 MB

// ---------------------------------------------------------------------------
// K1: fused x-scan + tile-local y-scan + transpose.
// Block = (b, 8-row ytile, 8 channels). Warp w owns channel w.
// All 8 row loads issued up front (MLP=8); one barrier; bulk write phase.
// ---------------------------------------------------------------------------
__global__ __launch_bounds__(256) void k1_fused(const float* __restrict__ x,
                                                float* __restrict__ S,
                                                float* __restrict__ cs) {
    const int bx = blockIdx.x;
    const int cg = bx & (NCG1_ - 1);          // 0..31
    const int yt = (bx >> 5) & (NT_ - 1);     // 0..15
    const int b  = bx >> 9;                   // 0..3

    const int tid  = threadIdx.x;
    const int lane = tid & 31;
    const int warp = tid >> 5;                // 8 warps = 8 channels
    const int cbase = cg * CG1_;

    // smem: [8 ch][pitch 1032] floats (pitch mult of 4 for float4, +8 pad)
    __shared__ __align__(16) float s[CG1_ * 1032];
    float4* s4 = reinterpret_cast<float4*>(s);
    const int P4 = 1032 / 4;                  // 258 float4 per channel row

    // load all 8 rows of this warp's channel (contiguous 4KB per warp)
    const float4* src4 = reinterpret_cast<const float4*>(
        x + ((size_t)(b * C_ + cbase + warp) * H_ + yt * YT_) * W_);
    float4 v[YT_];
    #pragma unroll
    for (int yy = 0; yy < YT_; yy++)
        v[yy] = src4[yy * 32 + lane];

    // per-row: local scan of 4 + warp shuffle scan + y-accumulate
    float4 acc = make_float4(0.f, 0.f, 0.f, 0.f);
    #pragma unroll
    for (int yy = 0; yy < YT_; yy++) {
        float4 w = v[yy];
        w.y += w.x; w.z += w.y; w.w += w.z;
        float sum = w.w;
        #pragma unroll
        for (int off = 1; off < 32; off <<= 1) {
            float t = __shfl_up_sync(0xffffffffu, sum, off);
            if (lane >= off) sum += t;
        }
        const float pre = sum - w.w;
        acc.x += w.x + pre;
        acc.y += w.y + pre;
        acc.z += w.z + pre;
        acc.w += w.w + pre;
        s4[warp * P4 + yy * 32 + lane] = acc;  // float4 smem store, no conflicts
    }
    __syncthreads();

    // bulk transposed write: S[((b*H + yt*8 + yy)*W + x)*C + cbase + cl]
    float* dstBase = S + ((size_t)(b * H_ + yt * YT_) * W_) * C_ + cbase;
    #pragma unroll 8
    for (int i = tid; i < CG1_ * YT_ * W_; i += 256) {
        const int cl   = i & (CG1_ - 1);
        const int rest = i >> 3;              // yy*128 + xx
        const int xx   = rest & (W_ - 1);
        const int yy   = rest >> 7;
        dstBase[((size_t)yy * W_ + xx) * C_ + cl] = s[cl * 1032 + yy * W_ + xx];
    }
    __syncthreads();

    // publish tile column sums
    s4[warp * P4 + lane] = acc;
    __syncthreads();
    float* csrow = cs + ((size_t)(b * NT_ + yt) * W_) * C_ + cbase;
    #pragma unroll 4
    for (int i = tid; i < CG1_ * W_; i += 256) {
        const int cl = i & (CG1_ - 1);
        const int xx = i >> 3;
        csrow[(size_t)xx * C_ + cl] = s[cl * 1032 + xx];
    }
}

// ---------------------------------------------------------------------------
// K2': exclusive scan of cs over the 16 y-tiles -> off. Thread per (b,x,c).
// ---------------------------------------------------------------------------
__global__ __launch_bounds__(256) void k2_tilescan(const float* __restrict__ cs,
                                                   float* __restrict__ off) {
    const int g   = blockIdx.x * 256 + threadIdx.x;   // 0 .. B*W*C-1
    const int b   = g >> 15;
    const int rem = g & 32767;
    size_t base = (size_t)b * (NT_ * W_ * C_) + rem;
    const size_t str = (size_t)W_ * C_;

    float acc = 0.f;
    #pragma unroll
    for (int t = 0; t < NT_; t++) {
        const float v = cs[base];
        off[base] = acc;
        acc += v;
        base += str;
    }
}

// ---------------------------------------------------------------------------
// K3: gather. Grid = (B*Q, 8 cgroups of 32 ch). 256 thr = 32 ch x 8 stripes.
// ---------------------------------------------------------------------------
__global__ __launch_bounds__(256) void k3_gather(const int* __restrict__ rois,
                                                 const float* __restrict__ S,
                                                 const float* __restrict__ off,
                                                 float* __restrict__ out) {
    const int bq = blockIdx.x;           // 0 .. B*Q-1
    const int cg = blockIdx.y;           // 0..7
    const int b  = bq / Q_;
    const int tid = threadIdx.x;

    __shared__ int   e_ys[OUT_], e_ye[OUT_], e_xs[OUT_], e_xe[OUT_];
    __shared__ float ia[BINS];
    __shared__ float stage[32][BINS + 2];   // pad 51 -> conflict-free

    const int* r = rois + bq * 5;        // [bidx, x1, y1, x2, y2]

    if (tid < OUT_) {
        int y1 = r[2], leny = r[4] - r[2];
        e_ys[tid] = y1 + (tid * leny) / OUT_;
        e_ye[tid] = y1 + ((tid + 1) * leny + (OUT_ - 1)) / OUT_;
    } else if (tid < 2 * OUT_) {
        int k = tid - OUT_;
        int x1 = r[1], lenx = r[3] - r[1];
        e_xs[k] = x1 + (k * lenx) / OUT_;
        e_xe[k] = x1 + ((k + 1) * lenx + (OUT_ - 1)) / OUT_;
    }
    __syncthreads();
    if (tid < BINS) {
        int oy = tid / OUT_, ox = tid % OUT_;
        ia[tid] = 1.0f / (float)((e_ye[oy] - e_ys[oy]) * (e_xe[ox] - e_xs[ox]));
    }
    __syncthreads();

    const int cl  = tid & 31;
    const int sub = tid >> 5;            // 0..7
    const int c   = cg * 32 + cl;
    const float* Sb = S   + (size_t)b * (H_ * W_ * C_);
    const float* Ob = off + (size_t)b * (NT_ * W_ * C_);

    #pragma unroll
    for (int bin = sub; bin < BINS; bin += 8) {
        const int oy = bin / OUT_, ox = bin % OUT_;
        const int Ys = e_ys[oy], Ye = e_ye[oy];
        const int Xs = e_xs[ox], Xe = e_xe[ox];

        auto corner = [&](int ey, int ex) -> float {
            if (ey == 0 || ex == 0) return 0.f;
            const size_t xi = (size_t)(ex - 1) * C_ + c;
            const float t = Sb[(size_t)(ey - 1) * (W_ * C_) + xi];
            const float o = Ob[(size_t)((ey - 1) >> 3) * (W_ * C_) + xi];
            return t + o;
        };

        const float see = corner(Ye, Xe);
        const float sse = corner(Ys, Xe);
        const float ses = corner(Ye, Xs);
        const float sss = corner(Ys, Xs);

        stage[cl][bin] = (see - sse - ses + sss) * ia[bin];
    }
    __syncthreads();

    // contiguous slab: out[(bq*C + cg*32 + cl)*49 + bin], 1568 floats
    float* ob = out + ((size_t)bq * C_ + cg * 32) * BINS;
    #pragma unroll 4
    for (int i = tid; i < 32 * BINS; i += 256) {
        ob[i] = stage[i / BINS][i % BINS];
    }
}

// ---------------------------------------------------------------------------
extern "C" void kernel_launch(void* const* d_in, const int* in_sizes, int n_in,
                              void* d_out, int out_size) {
    const float* x    = (const float*)d_in[0];
    const int*   rois = (const int*)d_in[1];
    float*       out  = (float*)d_out;

    float *sat, *cs, *off;
    cudaGetSymbolAddress((void**)&sat, g_sat);
    cudaGetSymbolAddress((void**)&cs,  g_cs);
    cudaGetSymbolAddress((void**)&off, g_off);

    k1_fused<<<B_ * NT_ * NCG1_, 256>>>(x, sat, cs);

    k2_tilescan<<<(B_ * W_ * C_) / 256, 256>>>(cs, off);

    dim3 g3(B_ * Q_, 8);
    k3_gather<<<g3, 256>>>(rois, sat, off, out);
}

// round 5
// speedup vs baseline: 1.1875x; 1.1875x over previous
#include <cuda_runtime.h>
#include <cstdint>

#define B_   4
#define C_   256
#define H_   128
#define W_   128
#define Q_   100
#define OUT_ 7
#define BINS (OUT_ * OUT_)   // 49

#define YT_  8               // rows per y-tile
#define NT_  (H_ / YT_)      // 16 y-tiles

// SAT layout: S[b][y][cgrp][x][8]  (cgrp = c>>3, 32 groups; 8 channels packed)
// Tile-local y-scan (within 8-row tiles). 64 MB.
__device__ float g_sat[(size_t)B_ * H_ * 32 * W_ * 8];
// Exclusive tile-prefix offsets: off[b][t][cgrp][x][8], 8 MB.
__device__ float g_off[(size_t)B_ * NT_ * 32 * W_ * 8];

// ---------------------------------------------------------------------------
// K1: fused x-scan + tile-local y-scan + repack.
// Block = (b, 8-row ytile, cgrp of 8 channels). Warp w owns channel w.
// Output per row is a CONTIGUOUS 4KB run -> perfect float4 stores.
// smem pitch 1036 (1036 % 32 == 12) -> conflict-free in both phases.
// ---------------------------------------------------------------------------
__global__ __launch_bounds__(256) void k1_fused(const float* __restrict__ x,
                                                float* __restrict__ S) {
    const int bx = blockIdx.x;
    const int cg = bx & 31;                   // channel group 0..31
    const int yt = (bx >> 5) & (NT_ - 1);     // 0..15
    const int b  = bx >> 9;                   // 0..3

    const int tid  = threadIdx.x;
    const int lane = tid & 31;
    const int warp = tid >> 5;                // 8 warps = 8 channels

    __shared__ __align__(16) float s[8 * 1036];
    float4* s4 = reinterpret_cast<float4*>(s);   // pitch 259 float4 per channel

    // load all 8 rows of this warp's channel (MLP=8)
    const float4* src4 = reinterpret_cast<const float4*>(
        x + ((size_t)(b * C_ + cg * 8 + warp) * H_ + yt * YT_) * W_);
    float4 v[YT_];
    #pragma unroll
    for (int yy = 0; yy < YT_; yy++)
        v[yy] = src4[yy * 32 + lane];

    // x-scan + running y-accumulate
    float4 acc = make_float4(0.f, 0.f, 0.f, 0.f);
    #pragma unroll
    for (int yy = 0; yy < YT_; yy++) {
        float4 w = v[yy];
        w.y += w.x; w.z += w.y; w.w += w.z;
        float sum = w.w;
        #pragma unroll
        for (int off = 1; off < 32; off <<= 1) {
            float t = __shfl_up_sync(0xffffffffu, sum, off);
            if (lane >= off) sum += t;
        }
        const float pre = sum - w.w;
        acc.x += w.x + pre;
        acc.y += w.y + pre;
        acc.z += w.z + pre;
        acc.w += w.w + pre;
        s4[warp * 259 + yy * 32 + lane] = acc;
    }
    __syncthreads();

    // repack + write: per yy a contiguous 1024-float run at
    // S[((b*H + yt*8 + yy)*32 + cg)*1024 + x*8 + c8]
    float4* S4 = reinterpret_cast<float4*>(S);
    #pragma unroll
    for (int it = 0; it < 8; it++) {
        const int k   = it * 256 + tid;       // 0..2047 float4s
        const int yy  = k >> 8;
        const int r   = k & 255;              // x*2 + cl4
        const int xx  = r >> 1;
        const int cl4 = (r & 1) * 4;
        float4 o;
        o.x = s[(cl4 + 0) * 1036 + yy * W_ + xx];
        o.y = s[(cl4 + 1) * 1036 + yy * W_ + xx];
        o.z = s[(cl4 + 2) * 1036 + yy * W_ + xx];
        o.w = s[(cl4 + 3) * 1036 + yy * W_ + xx];
        S4[((size_t)((b * H_ + yt * YT_ + yy) * 32 + cg)) * 256 + r] = o;
    }
}

// ---------------------------------------------------------------------------
// K2: exclusive tile-prefix. Tile column sum == SAT row y = t*8+7.
// Thread per (b, cgrp, x, c8) -> fully coalesced.
// ---------------------------------------------------------------------------
__global__ __launch_bounds__(256) void k2_tilescan(const float* __restrict__ S,
                                                   float* __restrict__ off) {
    const int g   = blockIdx.x * 256 + threadIdx.x;   // 0 .. B*32768-1
    const int b   = g >> 15;
    const int rem = g & 32767;

    float acc = 0.f;
    #pragma unroll
    for (int t = 0; t < NT_; t++) {
        off[(size_t)(b * NT_ + t) * 32768 + rem] = acc;
        acc += S[(size_t)(b * H_ + t * YT_ + 7) * 32768 + rem];
    }
}

// ---------------------------------------------------------------------------
// K3: gather. Grid = (B*Q, 8 cgroups of 32 ch).
// Thread handles 4 channels via float4; 8 lanes x 32 bin-stripes.
// corner = tile-local SAT + tile offset (both float4).
// ---------------------------------------------------------------------------
__device__ __forceinline__ float4 f4add(float4 a, float4 b) {
    return make_float4(a.x + b.x, a.y + b.y, a.z + b.z, a.w + b.w);
}

__global__ __launch_bounds__(256) void k3_gather(const int* __restrict__ rois,
                                                 const float* __restrict__ S,
                                                 const float* __restrict__ off,
                                                 float* __restrict__ out) {
    const int bq = blockIdx.x;           // 0 .. B*Q-1
    const int cg = blockIdx.y;           // 0..7  (32 channels)
    const int b  = bq / Q_;
    const int tid = threadIdx.x;

    __shared__ int   e_ys[OUT_], e_ye[OUT_], e_xs[OUT_], e_xe[OUT_];
    __shared__ float ia[BINS];
    __shared__ float stage[32 * 51];     // pitch 51 -> conflict-free

    const int* r = rois + bq * 5;        // [bidx, x1, y1, x2, y2]

    if (tid < OUT_) {
        int y1 = r[2], leny = r[4] - r[2];
        e_ys[tid] = y1 + (tid * leny) / OUT_;
        e_ye[tid] = y1 + ((tid + 1) * leny + (OUT_ - 1)) / OUT_;
    } else if (tid < 2 * OUT_) {
        int k = tid - OUT_;
        int x1 = r[1], lenx = r[3] - r[1];
        e_xs[k] = x1 + (k * lenx) / OUT_;
        e_xe[k] = x1 + ((k + 1) * lenx + (OUT_ - 1)) / OUT_;
    }
    __syncthreads();
    if (tid < BINS) {
        int oy = tid / OUT_, ox = tid % OUT_;
        ia[tid] = 1.0f / (float)((e_ye[oy] - e_ys[oy]) * (e_xe[ox] - e_xs[ox]));
    }
    __syncthreads();

    const int lane4 = tid & 7;           // 8 lanes x float4 = 32 channels
    const int sub   = tid >> 3;          // 0..31 bin stripes
    const int grp   = cg * 4 + (lane4 >> 1);   // cgrp of the 4 channels
    const int half  = lane4 & 1;               // which float4 within packet

    const float4* Sb4 = reinterpret_cast<const float4*>(S)
                      + (size_t)b * (H_ * 32 * 256);
    const float4* Ob4 = reinterpret_cast<const float4*>(off)
                      + (size_t)b * (NT_ * 32 * 256);

    const float4 zero = make_float4(0.f, 0.f, 0.f, 0.f);

    for (int bin = sub; bin < BINS; bin += 32) {
        const int oy = bin / OUT_, ox = bin % OUT_;
        const int Ys = e_ys[oy], Ye = e_ye[oy];
        const int Xs = e_xs[ox], Xe = e_xe[ox];

        auto corner = [&](int ey, int ex) -> float4 {
            if (ey == 0 || ex == 0) return zero;
            const int y = ey - 1, xx = ex - 1;
            const size_t si = ((size_t)(y * 32 + grp)) * 256 + xx * 2 + half;
            const size_t oi = ((size_t)((y >> 3) * 32 + grp)) * 256 + xx * 2 + half;
            return f4add(Sb4[si], Ob4[oi]);
        };

        const float4 see = corner(Ye, Xe);
        const float4 sse = corner(Ys, Xe);
        const float4 ses = corner(Ye, Xs);
        const float4 sss = corner(Ys, Xs);
        const float a = ia[bin];

        const int row = lane4 * 4;
        stage[(row + 0) * 51 + bin] = (see.x - sse.x - ses.x + sss.x) * a;
        stage[(row + 1) * 51 + bin] = (see.y - sse.y - ses.y + sss.y) * a;
        stage[(row + 2) * 51 + bin] = (see.z - sse.z - ses.z + sss.z) * a;
        stage[(row + 3) * 51 + bin] = (see.w - sse.w - ses.w + sss.w) * a;
    }
    __syncthreads();

    // contiguous slab: out[(bq*256 + cg*32 + ch)*49 + bin], 1568 floats
    float* ob = out + ((size_t)bq * C_ + cg * 32) * BINS;
    #pragma unroll
    for (int i = tid; i < 32 * BINS; i += 256) {
        ob[i] = stage[(i / BINS) * 51 + (i % BINS)];
    }
}

// ---------------------------------------------------------------------------
extern "C" void kernel_launch(void* const* d_in, const int* in_sizes, int n_in,
                              void* d_out, int out_size) {
    const float* x    = (const float*)d_in[0];
    const int*   rois = (const int*)d_in[1];
    float*       out  = (float*)d_out;

    float *sat, *off;
    cudaGetSymbolAddress((void**)&sat, g_sat);
    cudaGetSymbolAddress((void**)&off, g_off);

    k1_fused<<<B_ * NT_ * 32, 256>>>(x, sat);

    k2_tilescan<<<(B_ * 32768) / 256, 256>>>(sat, off);

    dim3 g3(B_ * Q_, 8);
    k3_gather<<<g3, 256>>>(rois, sat, off, out);
}

// round 6
// speedup vs baseline: 1.2863x; 1.0832x over previous
#include <cuda_runtime.h>
#include <cstdint>

#define B_   4
#define C_   256
#define H_   128
#define W_   128
#define Q_   100
#define OUT_ 7
#define BINS (OUT_ * OUT_)   // 49

#define YT_  4               // rows per y-tile
#define NT_  (H_ / YT_)      // 32 y-tiles

// SAT, tile-local y-scan, FULL channel-last: S[b][y][x][c], 64 MB.
__device__ float g_sat[(size_t)B_ * H_ * W_ * C_];
// Exclusive tile-prefix: off[b][t][x][c], 16 MB.
__device__ float g_off[(size_t)B_ * NT_ * W_ * C_];

// per-channel smem offset: conflict-free in BOTH phases (see analysis)
__device__ __forceinline__ int cloff(int cl) { return cl * 520 + (cl >> 2) * 4; }

// ---------------------------------------------------------------------------
// K1: fused x-scan + 4-row tile y-scan + transpose to channel-last.
// Block = (b, yt4, cg of 32 ch). 512 threads = 16 warps; warp owns channels
// {warp, warp+16}. All 8 row-loads issued up front (MLP=8). One barrier.
// Write-out: channel-quad gather from smem (conflict-free via cloff) ->
// float4 stores, full 128B lines.
// ---------------------------------------------------------------------------
__global__ __launch_bounds__(512, 2) void k1_fused(const float* __restrict__ x,
                                                   float* __restrict__ S) {
    const int bx = blockIdx.x;
    const int cg = bx & 7;                    // 8 groups of 32 channels
    const int yt = (bx >> 3) & (NT_ - 1);     // 0..31
    const int b  = bx >> 8;                   // 0..3

    const int tid  = threadIdx.x;
    const int lane = tid & 31;
    const int warp = tid >> 5;                // 0..15

    __shared__ __align__(16) float s[16672];
    float4* s4 = reinterpret_cast<float4*>(s);

    // load both channels' 4 rows up front
    const float4* src0 = reinterpret_cast<const float4*>(
        x + ((size_t)(b * C_ + cg * 32 + warp) * H_ + yt * YT_) * W_);
    const float4* src1 = src0 + (size_t)16 * H_ * W_ / 4;   // channel +16

    float4 v0[YT_], v1[YT_];
    #pragma unroll
    for (int r = 0; r < YT_; r++) v0[r] = src0[r * 32 + lane];
    #pragma unroll
    for (int r = 0; r < YT_; r++) v1[r] = src1[r * 32 + lane];

    #pragma unroll
    for (int k = 0; k < 2; k++) {
        const int cl = warp + 16 * k;
        float4* vv = k ? v1 : v0;
        float4 acc = make_float4(0.f, 0.f, 0.f, 0.f);
        const int sb = cloff(cl) / 4;         // float4 base, aligned
        #pragma unroll
        for (int yy = 0; yy < YT_; yy++) {
            float4 w = vv[yy];
            w.y += w.x; w.z += w.y; w.w += w.z;
            float sum = w.w;
            #pragma unroll
            for (int off = 1; off < 32; off <<= 1) {
                float t = __shfl_up_sync(0xffffffffu, sum, off);
                if (lane >= off) sum += t;
            }
            const float pre = sum - w.w;
            acc.x += w.x + pre;
            acc.y += w.y + pre;
            acc.z += w.z + pre;
            acc.w += w.w + pre;
            s4[sb + yy * 32 + lane] = acc;
        }
    }
    __syncthreads();

    // write-out: 4096 float4 outputs; f = (yy*128 + xx)*8 + cq
    float4* S4 = reinterpret_cast<float4*>(S);
    const size_t obase = ((size_t)(b * H_ + yt * YT_)) * (W_ * C_ / 4) + cg * 8;
    #pragma unroll
    for (int it = 0; it < 8; it++) {
        const int f  = it * 512 + tid;
        const int cq = f & 7;                 // channel quad 0..7
        const int xx = (f >> 3) & 127;
        const int yy = f >> 10;
        float4 o;
        o.x = s[cloff(4 * cq + 0) + yy * 128 + xx];
        o.y = s[cloff(4 * cq + 1) + yy * 128 + xx];
        o.z = s[cloff(4 * cq + 2) + yy * 128 + xx];
        o.w = s[cloff(4 * cq + 3) + yy * 128 + xx];
        S4[obase + ((size_t)yy * W_ + xx) * (C_ / 4) + cq] = o;
    }
}

// ---------------------------------------------------------------------------
// K2: exclusive tile prefix over 32 tiles. Tile column-sum == SAT row
// y = t*4+3. Thread per (b, x, c) -> fully coalesced.
// ---------------------------------------------------------------------------
__global__ __launch_bounds__(256) void k2_tilescan(const float* __restrict__ S,
                                                   float* __restrict__ off) {
    const int g   = blockIdx.x * 256 + threadIdx.x;   // 0 .. B*32768-1
    const int b   = g >> 15;
    const int rem = g & 32767;

    float acc = 0.f;
    #pragma unroll
    for (int t = 0; t < NT_; t++) {
        off[(size_t)(b * NT_ + t) * 32768 + rem] = acc;
        acc += S[(size_t)(b * H_ + t * YT_ + 3) * 32768 + rem];
    }
}

// ---------------------------------------------------------------------------
// K3: gather. Grid = (B*Q, 4 cgroups of 64 ch). 256 thr = 16 ch-float4 lanes
// x 16 bin stripes. Corner = 256B contiguous -> wavefront-optimal loads.
// ---------------------------------------------------------------------------
__device__ __forceinline__ float4 f4add(float4 a, float4 b) {
    return make_float4(a.x + b.x, a.y + b.y, a.z + b.z, a.w + b.w);
}

__global__ __launch_bounds__(256) void k3_gather(const int* __restrict__ rois,
                                                 const float* __restrict__ S,
                                                 const float* __restrict__ off,
                                                 float* __restrict__ out) {
    const int bq = blockIdx.x;           // 0 .. B*Q-1
    const int cg = blockIdx.y;           // 0..3 (64 channels)
    const int b  = bq / Q_;
    const int tid = threadIdx.x;

    __shared__ int   e_ys[OUT_], e_ye[OUT_], e_xs[OUT_], e_xe[OUT_];
    __shared__ float ia[BINS];
    __shared__ float stage[64 * 51];

    const int* r = rois + bq * 5;        // [bidx, x1, y1, x2, y2]

    if (tid < OUT_) {
        int y1 = r[2], leny = r[4] - r[2];
        e_ys[tid] = y1 + (tid * leny) / OUT_;
        e_ye[tid] = y1 + ((tid + 1) * leny + (OUT_ - 1)) / OUT_;
    } else if (tid < 2 * OUT_) {
        int k = tid - OUT_;
        int x1 = r[1], lenx = r[3] - r[1];
        e_xs[k] = x1 + (k * lenx) / OUT_;
        e_xe[k] = x1 + ((k + 1) * lenx + (OUT_ - 1)) / OUT_;
    }
    __syncthreads();
    if (tid < BINS) {
        int oy = tid / OUT_, ox = tid % OUT_;
        ia[tid] = 1.0f / (float)((e_ye[oy] - e_ys[oy]) * (e_xe[ox] - e_xs[ox]));
    }
    __syncthreads();

    const int lane16 = tid & 15;         // channel float4 within 64-ch group
    const int sub    = tid >> 4;         // 0..15 bin stripes
    const int c4     = cg * 16 + lane16; // global channel-quad 0..63

    const float4* Sb4 = reinterpret_cast<const float4*>(S)
                      + (size_t)b * (H_ * W_ * C_ / 4);
    const float4* Ob4 = reinterpret_cast<const float4*>(off)
                      + (size_t)b * (NT_ * W_ * C_ / 4);

    const float4 zero = make_float4(0.f, 0.f, 0.f, 0.f);

    for (int bin = sub; bin < BINS; bin += 16) {
        const int oy = bin / OUT_, ox = bin % OUT_;
        const int Ys = e_ys[oy], Ye = e_ye[oy];
        const int Xs = e_xs[ox], Xe = e_xe[ox];

        auto corner = [&](int ey, int ex) -> float4 {
            if (ey == 0 || ex == 0) return zero;
            const int y = ey - 1, xx = ex - 1;
            const float4 sv = Sb4[((size_t)y * W_ + xx) * 64 + c4];
            const float4 ov = Ob4[((size_t)(y >> 2) * W_ + xx) * 64 + c4];
            return f4add(sv, ov);
        };

        const float4 see = corner(Ye, Xe);
        const float4 sse = corner(Ys, Xe);
        const float4 ses = corner(Ye, Xs);
        const float4 sss = corner(Ys, Xs);
        const float a = ia[bin];

        const int row = lane16 * 4;
        stage[(row + 0) * 51 + bin] = (see.x - sse.x - ses.x + sss.x) * a;
        stage[(row + 1) * 51 + bin] = (see.y - sse.y - ses.y + sss.y) * a;
        stage[(row + 2) * 51 + bin] = (see.z - sse.z - ses.z + sss.z) * a;
        stage[(row + 3) * 51 + bin] = (see.w - sse.w - ses.w + sss.w) * a;
    }
    __syncthreads();

    // contiguous slab: out[(bq*256 + cg*64 + ch)*49 + bin], 3136 floats
    float* ob = out + ((size_t)bq * C_ + cg * 64) * BINS;
    #pragma unroll
    for (int i = tid; i < 64 * BINS; i += 256) {
        ob[i] = stage[(i / BINS) * 51 + (i % BINS)];
    }
}

// ---------------------------------------------------------------------------
extern "C" void kernel_launch(void* const* d_in, const int* in_sizes, int n_in,
                              void* d_out, int out_size) {
    const float* x    = (const float*)d_in[0];
    const int*   rois = (const int*)d_in[1];
    float*       out  = (float*)d_out;

    float *sat, *off;
    cudaGetSymbolAddress((void**)&sat, g_sat);
    cudaGetSymbolAddress((void**)&off, g_off);

    k1_fused<<<B_ * NT_ * 8, 512>>>(x, sat);

    k2_tilescan<<<(B_ * 32768) / 256, 256>>>(sat, off);

    dim3 g3(B_ * Q_, 4);
    k3_gather<<<g3, 256>>>(rois, sat, off, out);
}

// round 8
// speedup vs baseline: 1.3525x; 1.0515x over previous
#include <cuda_runtime.h>
#include <cstdint>

#define B_   4
#define C_   256
#define H_   128
#define W_   128
#define Q_   100
#define OUT_ 7
#define BINS (OUT_ * OUT_)   // 49

#define YT_  4               // rows per y-tile
#define NT_  (H_ / YT_)      // 32 y-tiles

// SAT, tile-local y-scan, channel-last: S[b][y][x][c], 64 MB.
__device__ float g_sat[(size_t)B_ * H_ * W_ * C_];
// Exclusive tile-prefix: off[b][t][x][c], 16 MB.
// Tile 0 is NEVER written and never needed nonzero: device globals are
// zero-initialized and K2 writes only t >= 1, so off[t=0] == 0 always.
__device__ float g_off[(size_t)B_ * NT_ * W_ * C_];

// per-channel smem offset; quad-stride 8 banks -> conflict-free in BOTH
// K1 phases (compute-store float4 consecutive; write-out {8*cq+xx} covers
// all 32 banks).
__device__ __forceinline__ int cloff(int cl) { return cl * 520 + (cl >> 2) * 8; }

// ---------------------------------------------------------------------------
// K1: fused x-scan + 4-row tile y-scan + transpose to channel-last.
// Block = (b, yt4, cg of 16 ch). 256 threads = 8 warps; warp owns channels
// {warp, warp+8}. All 8 row-loads up front (MLP=8). One barrier.
// smem ~33KB -> 4 blocks/SM (reg-limited), sector-optimal 64B store chunks.
// ---------------------------------------------------------------------------
__global__ __launch_bounds__(256, 4) void k1_fused(const float* __restrict__ x,
                                                   float* __restrict__ S) {
    const int bx = blockIdx.x;
    const int cg = bx & 15;                   // 16 groups of 16 channels
    const int yt = (bx >> 4) & (NT_ - 1);     // 0..31
    const int b  = bx >> 9;                   // 0..3

    const int tid  = threadIdx.x;
    const int lane = tid & 31;
    const int warp = tid >> 5;                // 0..7

    __shared__ __align__(16) float s[16 * 520 + 32];
    float4* s4 = reinterpret_cast<float4*>(s);

    const float4* src0 = reinterpret_cast<const float4*>(
        x + ((size_t)(b * C_ + cg * 16 + warp) * H_ + yt * YT_) * W_);
    const float4* src1 = src0 + (size_t)8 * H_ * W_ / 4;   // channel +8

    float4 v0[YT_], v1[YT_];
    #pragma unroll
    for (int r = 0; r < YT_; r++) v0[r] = src0[r * 32 + lane];
    #pragma unroll
    for (int r = 0; r < YT_; r++) v1[r] = src1[r * 32 + lane];

    #pragma unroll
    for (int k = 0; k < 2; k++) {
        const int cl = warp + 8 * k;
        float4* vv = k ? v1 : v0;
        float4 acc = make_float4(0.f, 0.f, 0.f, 0.f);
        const int sb = cloff(cl) / 4;
        #pragma unroll
        for (int yy = 0; yy < YT_; yy++) {
            float4 w = vv[yy];
            w.y += w.x; w.z += w.y; w.w += w.z;
            float sum = w.w;
            #pragma unroll
            for (int off = 1; off < 32; off <<= 1) {
                float t = __shfl_up_sync(0xffffffffu, sum, off);
                if (lane >= off) sum += t;
            }
            const float pre = sum - w.w;
            acc.x += w.x + pre;
            acc.y += w.y + pre;
            acc.z += w.z + pre;
            acc.w += w.w + pre;
            s4[sb + yy * 32 + lane] = acc;
        }
    }
    __syncthreads();

    // write-out: 2048 float4; f = ((yy*128 + xx)*4 + cq)
    float4* S4 = reinterpret_cast<float4*>(S);
    const size_t obase = ((size_t)(b * H_ + yt * YT_)) * (W_ * C_ / 4) + cg * 4;
    #pragma unroll
    for (int it = 0; it < 8; it++) {
        const int f  = it * 256 + tid;
        const int cq = f & 3;                 // channel quad 0..3
        const int xx = (f >> 2) & 127;
        const int yy = f >> 9;
        float4 o;
        o.x = s[cloff(4 * cq + 0) + yy * 128 + xx];
        o.y = s[cloff(4 * cq + 1) + yy * 128 + xx];
        o.z = s[cloff(4 * cq + 2) + yy * 128 + xx];
        o.w = s[cloff(4 * cq + 3) + yy * 128 + xx];
        S4[obase + ((size_t)yy * W_ + xx) * (C_ / 4) + cq] = o;
    }
}

// ---------------------------------------------------------------------------
// K2: exclusive tile prefix (float4). Tile column-sum == SAT row y = t*4+3.
// Tile 0 never written (stays zero). Grid covers all batches.
// ---------------------------------------------------------------------------
__global__ __launch_bounds__(256) void k2_tilescan(const float4* __restrict__ S4,
                                                   float4* __restrict__ off4) {
    const int g   = blockIdx.x * 256 + threadIdx.x;   // 0 .. B*8192-1
    const int b   = g >> 13;
    const int rem = g & 8191;
    const float4* Sb = S4 + (size_t)b * (H_ * W_ * C_ / 4);
    float4* Ob = off4 + (size_t)b * (NT_ * W_ * C_ / 4);

    float4 acc = Sb[(size_t)3 * 8192 + rem];
    #pragma unroll
    for (int t = 1; t < NT_; t++) {
        Ob[(size_t)t * 8192 + rem] = acc;
        if (t < NT_ - 1) {
            const float4 v = Sb[(size_t)(t * YT_ + 3) * 8192 + rem];
            acc.x += v.x; acc.y += v.y; acc.z += v.z; acc.w += v.w;
        }
    }
}

// ---------------------------------------------------------------------------
// K3: gather. Grid = (B*Q, 4 cgroups of 64 ch). 256 thr = 16 ch-quads x
// 16 bin stripes; each thread evaluates 3 bins straight-line (24 loads of
// MLP). off tile-0 reads return zeros by construction -> no guard needed.
// ---------------------------------------------------------------------------
__global__ __launch_bounds__(256) void k3_gather(const int* __restrict__ rois,
                                                 const float* __restrict__ S,
                                                 const float* __restrict__ off,
                                                 float* __restrict__ out) {
    const int bq = blockIdx.x;           // 0 .. B*Q-1
    const int cg = blockIdx.y;           // 0..3 (64 channels)
    const int b  = bq / Q_;
    const int tid = threadIdx.x;

    __shared__ int   e_ys[OUT_], e_ye[OUT_], e_xs[OUT_], e_xe[OUT_];
    __shared__ float ia[BINS];
    __shared__ float stage[64 * 51];

    const int* r = rois + bq * 5;        // [bidx, x1, y1, x2, y2]

    if (tid < OUT_) {
        int y1 = r[2], leny = r[4] - r[2];
        e_ys[tid] = y1 + (tid * leny) / OUT_;
        e_ye[tid] = y1 + ((tid + 1) * leny + (OUT_ - 1)) / OUT_;
    } else if (tid < 2 * OUT_) {
        int k = tid - OUT_;
        int x1 = r[1], lenx = r[3] - r[1];
        e_xs[k] = x1 + (k * lenx) / OUT_;
        e_xe[k] = x1 + ((k + 1) * lenx + (OUT_ - 1)) / OUT_;
    }
    __syncthreads();
    if (tid < BINS) {
        int oy = tid / OUT_, ox = tid % OUT_;
        ia[tid] = 1.0f / (float)((e_ye[oy] - e_ys[oy]) * (e_xe[ox] - e_xs[ox]));
    }
    __syncthreads();

    const int lane16 = tid & 15;
    const int sub    = tid >> 4;         // 0..15
    const int c4     = cg * 16 + lane16;

    const float4* Sb4 = reinterpret_cast<const float4*>(S)
                      + (size_t)b * (H_ * W_ * C_ / 4);
    const float4* Ob4 = reinterpret_cast<const float4*>(off)
                      + (size_t)b * (NT_ * W_ * C_ / 4);

    auto evalbin = [&](int bin) -> float4 {
        const int oy = bin / OUT_, ox = bin % OUT_;
        const int ye = e_ye[oy] - 1, xe = e_xe[ox] - 1;   // always >= 0
        const int ys = e_ys[oy] - 1, xs = e_xs[ox] - 1;   // may be -1
        const bool hy = (ys >= 0), hx = (xs >= 0);
        const int ysc = hy ? ys : 0, xsc = hx ? xs : 0;
        const int tye = ye >> 2, tys = ysc >> 2;

        float4 a = Sb4[((size_t)ye * W_ + xe) * 64 + c4];
        float4 t;
        t = Sb4[((size_t)ysc * W_ + xe) * 64 + c4];
        if (hy) { a.x -= t.x; a.y -= t.y; a.z -= t.z; a.w -= t.w; }
        t = Sb4[((size_t)ye * W_ + xsc) * 64 + c4];
        if (hx) { a.x -= t.x; a.y -= t.y; a.z -= t.z; a.w -= t.w; }
        t = Sb4[((size_t)ysc * W_ + xsc) * 64 + c4];
        if (hy && hx) { a.x += t.x; a.y += t.y; a.z += t.z; a.w += t.w; }

        t = Ob4[((size_t)tye * W_ + xe) * 64 + c4];
        a.x += t.x; a.y += t.y; a.z += t.z; a.w += t.w;
        t = Ob4[((size_t)tys * W_ + xe) * 64 + c4];
        if (hy) { a.x -= t.x; a.y -= t.y; a.z -= t.z; a.w -= t.w; }
        t = Ob4[((size_t)tye * W_ + xsc) * 64 + c4];
        if (hx) { a.x -= t.x; a.y -= t.y; a.z -= t.z; a.w -= t.w; }
        t = Ob4[((size_t)tys * W_ + xsc) * 64 + c4];
        if (hy && hx) { a.x += t.x; a.y += t.y; a.z += t.z; a.w += t.w; }

        const float sc = ia[bin];
        return make_float4(a.x * sc, a.y * sc, a.z * sc, a.w * sc);
    };

    auto stput = [&](int bin, float4 v) {
        const int row = lane16 * 4;
        stage[(row + 0) * 51 + bin] = v.x;
        stage[(row + 1) * 51 + bin] = v.y;
        stage[(row + 2) * 51 + bin] = v.z;
        stage[(row + 3) * 51 + bin] = v.w;
    };

    const float4 r0 = evalbin(sub);
    const float4 r1 = evalbin(sub + 16);
    const float4 r2 = evalbin(sub + 32);
    stput(sub,      r0);
    stput(sub + 16, r1);
    stput(sub + 32, r2);
    if (sub == 0) stput(48, evalbin(48));
    __syncthreads();

    // contiguous slab: out[(bq*256 + cg*64 + ch)*49 + bin], 3136 floats
    float* ob = out + ((size_t)bq * C_ + cg * 64) * BINS;
    #pragma unroll
    for (int i = tid; i < 64 * BINS; i += 256) {
        ob[i] = stage[(i / BINS) * 51 + (i % BINS)];
    }
}

// ---------------------------------------------------------------------------
extern "C" void kernel_launch(void* const* d_in, const int* in_sizes, int n_in,
                              void* d_out, int out_size) {
    const float* x    = (const float*)d_in[0];
    const int*   rois = (const int*)d_in[1];
    float*       out  = (float*)d_out;

    float *sat, *off;
    cudaGetSymbolAddress((void**)&sat, g_sat);
    cudaGetSymbolAddress((void**)&off, g_off);

    k1_fused<<<B_ * NT_ * 16, 256>>>(x, sat);

    k2_tilescan<<<(B_ * 8192) / 256, 256>>>((const float4*)sat, (float4*)off);

    dim3 g3(B_ * Q_, 4);
    k3_gather<<<g3, 256>>>(rois, sat, off, out);
}